// round 1
// baseline (speedup 1.0000x reference)
#include <cuda_runtime.h>

#define NN 50000
#define EE 800000
#define CC 64
#define KK 4
#define DD 3
#define WCOLS 320   // 256 (g) + 64 (root+dense)

// ---------------- device scratch (static, allocation-free) ----------------
__device__ float  d_W[CC * WCOLS];      // fused weight [64][320]
__device__ float  d_gauss[24];          // mu[12], inv[12] = 0.5/(eps+sigma^2)
__device__ float  d_Y[NN * WCOLS];      // x @ W   (64 MB)
__device__ float  d_msg[NN * CC];       // scatter-add target
__device__ float  d_cnt[NN];            // edge counts per dst (shared across layers)
__device__ float  d_h[NN * CC];         // layer-0 output
__device__ double d_stats[2 * CC];      // BN sum / sumsq
__device__ float  d_bnA[CC];            // BN scale
__device__ float  d_bnB[CC];            // BN shift

// ---------------- prep: build fused weight + gaussian params ----------------
__global__ void prep_kernel(const float* __restrict__ g, const float* __restrict__ root,
                            const float* __restrict__ dense, const float* __restrict__ mu,
                            const float* __restrict__ sigma) {
    int tid = threadIdx.x + blockIdx.x * blockDim.x;
    for (int i = tid; i < CC * WCOLS; i += blockDim.x * gridDim.x) {
        int c = i / WCOLS, j = i - c * WCOLS;
        float v;
        if (j < KK * CC) v = g[c * (KK * CC) + j];
        else             v = root[c * CC + (j - KK * CC)] + dense[c * CC + (j - KK * CC)];
        d_W[i] = v;
    }
    if (tid < KK * DD) {
        d_gauss[tid] = mu[tid];
        float s = sigma[tid];
        d_gauss[KK * DD + tid] = 0.5f / (1e-15f + s * s);
    }
}

// ---------------- zero scratch ----------------
__global__ void zero_kernel(int do_cnt, int n) {
    int i = threadIdx.x + blockIdx.x * blockDim.x;
    int n16 = n * (CC / 4);
    if (i < n16) reinterpret_cast<float4*>(d_msg)[i] = make_float4(0.f, 0.f, 0.f, 0.f);
    if (i < 2 * CC) d_stats[i] = 0.0;
    if (do_cnt && i < n) d_cnt[i] = 0.f;
}

// ---------------- GEMM: Y[N,320] = X[N,64] @ W[64,320] ----------------
// 64x64 output tile per block, 256 threads, 4x4 microtile, K=64 single stage.
__global__ void gemm_kernel(const float* Xin, int use_h, int nrows) {
    const float* X = use_h ? d_h : Xin;
    __shared__ float sA[64 * 64];
    __shared__ float sB[64 * 64];
    int tid  = threadIdx.x;
    int row0 = blockIdx.x * 64;
    int col0 = blockIdx.y * 64;

#pragma unroll
    for (int i = 0; i < 4; i++) {
        int t  = tid + i * 256;
        int r  = t >> 4;
        int c4 = (t & 15) << 2;
        float4 v = make_float4(0.f, 0.f, 0.f, 0.f);
        if (row0 + r < nrows)
            v = *reinterpret_cast<const float4*>(X + (size_t)(row0 + r) * CC + c4);
        *reinterpret_cast<float4*>(sA + r * 64 + c4) = v;
        *reinterpret_cast<float4*>(sB + r * 64 + c4) =
            *reinterpret_cast<const float4*>(d_W + r * WCOLS + col0 + c4);
    }
    __syncthreads();

    int tx = tid & 15, ty = tid >> 4;
    float acc[4][4];
#pragma unroll
    for (int i = 0; i < 4; i++)
#pragma unroll
        for (int j = 0; j < 4; j++) acc[i][j] = 0.f;

#pragma unroll 8
    for (int k = 0; k < 64; k++) {
        float4 b = *reinterpret_cast<float4*>(sB + k * 64 + (tx << 2));
        float a0 = sA[(ty * 4 + 0) * 64 + k];
        float a1 = sA[(ty * 4 + 1) * 64 + k];
        float a2 = sA[(ty * 4 + 2) * 64 + k];
        float a3 = sA[(ty * 4 + 3) * 64 + k];
        acc[0][0] += a0 * b.x; acc[0][1] += a0 * b.y; acc[0][2] += a0 * b.z; acc[0][3] += a0 * b.w;
        acc[1][0] += a1 * b.x; acc[1][1] += a1 * b.y; acc[1][2] += a1 * b.z; acc[1][3] += a1 * b.w;
        acc[2][0] += a2 * b.x; acc[2][1] += a2 * b.y; acc[2][2] += a2 * b.z; acc[2][3] += a2 * b.w;
        acc[3][0] += a3 * b.x; acc[3][1] += a3 * b.y; acc[3][2] += a3 * b.z; acc[3][3] += a3 * b.w;
    }

#pragma unroll
    for (int i = 0; i < 4; i++) {
        int r = row0 + ty * 4 + i;
        if (r < nrows) {
            float4 v = make_float4(acc[i][0], acc[i][1], acc[i][2], acc[i][3]);
            *reinterpret_cast<float4*>(d_Y + (size_t)r * WCOLS + col0 + (tx << 2)) = v;
        }
    }
}

// ---------------- edge kernel: gather xg[src], weight by gaussian, RED into msg[dst] ----
// 16 lanes per edge; each lane owns 4 channels (one float4).
__global__ void edge_kernel(const int* __restrict__ edges, const float* __restrict__ pseudo,
                            int do_cnt, int nE) {
    int tid  = threadIdx.x + blockIdx.x * blockDim.x;
    int e    = tid >> 4;
    int lane = tid & 15;
    if (e >= nE) return;

    int src = edges[e];
    int dst = edges[nE + e];

    float p0 = pseudo[e * 3 + 0];
    float p1 = pseudo[e * 3 + 1];
    float p2 = pseudo[e * 3 + 2];

    float w[KK];
#pragma unroll
    for (int k = 0; k < KK; k++) {
        float q0 = p0 - d_gauss[k * 3 + 0];
        float q1 = p1 - d_gauss[k * 3 + 1];
        float q2 = p2 - d_gauss[k * 3 + 2];
        float t = q0 * q0 * d_gauss[12 + k * 3 + 0]
                + q1 * q1 * d_gauss[12 + k * 3 + 1]
                + q2 * q2 * d_gauss[12 + k * 3 + 2];
        w[k] = __expf(-t);
    }

    const float4* yb = reinterpret_cast<const float4*>(d_Y + (size_t)src * WCOLS);
    float4 acc = make_float4(0.f, 0.f, 0.f, 0.f);
#pragma unroll
    for (int k = 0; k < KK; k++) {
        float4 v = yb[k * 16 + lane];
        acc.x += w[k] * v.x; acc.y += w[k] * v.y;
        acc.z += w[k] * v.z; acc.w += w[k] * v.w;
    }

    float* mp = d_msg + (size_t)dst * CC + lane * 4;
    unsigned long long gp;
    asm("cvta.to.global.u64 %0, %1;" : "=l"(gp) : "l"(mp));
    asm volatile("red.global.add.v4.f32 [%0], {%1,%2,%3,%4};"
                 :: "l"(gp), "f"(acc.x), "f"(acc.y), "f"(acc.z), "f"(acc.w) : "memory");

    if (do_cnt && lane == 0) atomicAdd(d_cnt + dst, 1.0f);
}

// ---------------- finalize: mean aggregation + linear + bias; BN stats ----------------
__global__ void finalize_kernel(const float* __restrict__ bias, float* out, int to_out, int n) {
    float* H = to_out ? out : d_h;
    int c = threadIdx.x;       // 64 channels
    int ty = threadIdx.y;      // 4 row groups
    int rbase = blockIdx.x * 128;
    float b = bias[c];
    double s = 0.0, s2 = 0.0;

    for (int i = ty; i < 128; i += 4) {
        int r = rbase + i;
        if (r < n) {
            float cv = fmaxf(d_cnt[r], 1.0f);
            float h = __fdividef(d_msg[(size_t)r * CC + c], cv)
                      + d_Y[(size_t)r * WCOLS + 256 + c] + b;
            H[(size_t)r * CC + c] = h;
            s += (double)h;
            s2 += (double)h * (double)h;
        }
    }

    __shared__ double sh[8][64];
    sh[ty][c] = s;
    sh[4 + ty][c] = s2;
    __syncthreads();
    if (ty == 0) {
        double t1 = sh[0][c] + sh[1][c] + sh[2][c] + sh[3][c];
        double t2 = sh[4][c] + sh[5][c] + sh[6][c] + sh[7][c];
        atomicAdd(&d_stats[c], t1);
        atomicAdd(&d_stats[CC + c], t2);
    }
}

// ---------------- BN prep: per-channel scale/shift ----------------
__global__ void bnprep_kernel(const float* __restrict__ gamma, const float* __restrict__ beta, int n) {
    int c = threadIdx.x;
    double mean = d_stats[c] / (double)n;
    double var  = d_stats[CC + c] / (double)n - mean * mean;
    double inv  = rsqrt(var + 1e-5);
    d_bnA[c] = (float)((double)gamma[c] * inv);
    d_bnB[c] = (float)((double)beta[c] - mean * (double)gamma[c] * inv);
}

// ---------------- BN apply (+ optional ReLU), in place ----------------
__global__ void bnapply_kernel(float* out, int to_out, int relu, int n) {
    float* H = to_out ? out : d_h;
    int i = threadIdx.x + blockIdx.x * blockDim.x;
    if (i >= n * (CC / 4)) return;
    float4 v = reinterpret_cast<float4*>(H)[i];
    int c4 = (i & 15) << 2;
    float4 a = *reinterpret_cast<float4*>(d_bnA + c4);
    float4 b = *reinterpret_cast<float4*>(d_bnB + c4);
    v.x = v.x * a.x + b.x;
    v.y = v.y * a.y + b.y;
    v.z = v.z * a.z + b.z;
    v.w = v.w * a.w + b.w;
    if (relu) {
        v.x = fmaxf(v.x, 0.f); v.y = fmaxf(v.y, 0.f);
        v.z = fmaxf(v.z, 0.f); v.w = fmaxf(v.w, 0.f);
    }
    reinterpret_cast<float4*>(H)[i] = v;
}

// ---------------- host orchestration ----------------
static void run_layer(const float* x, int use_h,
                      const float* g, const float* mu, const float* sigma,
                      const float* root, const float* bias, const float* dense,
                      const float* gamma, const float* beta,
                      float* out, int to_out, int layer0,
                      int N, int E, const int* edges, const float* pseudo) {
    prep_kernel<<<40, 512>>>(g, root, dense, mu, sigma);
    zero_kernel<<<(N * 16 + 255) / 256, 256>>>(layer0, N);
    dim3 ggrid((N + 63) / 64, WCOLS / 64);
    gemm_kernel<<<ggrid, 256>>>(x, use_h, N);
    edge_kernel<<<(E * 16 + 255) / 256, 256>>>(edges, pseudo, layer0, E);
    finalize_kernel<<<(N + 127) / 128, dim3(64, 4)>>>(bias, out, to_out, N);
    bnprep_kernel<<<1, 64>>>(gamma, beta, N);
    bnapply_kernel<<<(N * 16 + 255) / 256, 256>>>(out, to_out, layer0, N);
}

extern "C" void kernel_launch(void* const* d_in, const int* in_sizes, int n_in,
                              void* d_out, int out_size) {
    const float* vals   = (const float*)d_in[0];
    const int*   edges  = (const int*)  d_in[1];
    const float* pseudo = (const float*)d_in[2];

    const float* g0     = (const float*)d_in[3];
    const float* mu0    = (const float*)d_in[4];
    const float* sigma0 = (const float*)d_in[5];
    const float* root0  = (const float*)d_in[6];
    const float* bias0  = (const float*)d_in[7];
    const float* dense0 = (const float*)d_in[8];
    const float* gamma0 = (const float*)d_in[9];
    const float* beta0  = (const float*)d_in[10];

    const float* g1     = (const float*)d_in[11];
    const float* mu1    = (const float*)d_in[12];
    const float* sigma1 = (const float*)d_in[13];
    const float* root1  = (const float*)d_in[14];
    const float* bias1  = (const float*)d_in[15];
    const float* dense1 = (const float*)d_in[16];
    const float* gamma1 = (const float*)d_in[17];
    const float* beta1  = (const float*)d_in[18];

    float* out = (float*)d_out;

    int N = in_sizes[0] / CC;       // 50000
    int E = in_sizes[1] / 2;        // 800000

    // layer 0: vals -> d_h (ReLU)
    run_layer(vals, /*use_h=*/0, g0, mu0, sigma0, root0, bias0, dense0, gamma0, beta0,
              out, /*to_out=*/0, /*layer0=*/1, N, E, edges, pseudo);
    // layer 1: d_h -> out (no ReLU)
    run_layer(nullptr, /*use_h=*/1, g1, mu1, sigma1, root1, bias1, dense1, gamma1, beta1,
              out, /*to_out=*/1, /*layer0=*/0, N, E, edges, pseudo);
}

// round 3
// speedup vs baseline: 1.5409x; 1.5409x over previous
#include <cuda_runtime.h>
#include <cuda_fp16.h>
#include <cstdint>

#define NN 50000
#define EE 800000
#define CC 64
#define KK 4
#define WCOLS 320
#define SAH 72    // sA stride in halves (64 + 8 pad): 16B-chunk advance 9 mod 8 = 1 -> conflict-free ldmatrix
#define SBH 136   // sB stride in halves (128 + 8 pad): chunk advance 17 mod 8 = 1 -> conflict-free

// ---------------- device scratch (static, allocation-free) ----------------
__device__ __align__(16) __half d_Wh[CC * 256];   // g weights, fp16
__device__ __align__(16) float  d_Wr[CC * CC];    // root + dense, fp32
__device__ float  d_gauss[24];                    // mu[12], inv[12] = 0.5/(eps+sigma^2)
__device__ __align__(16) __half d_Yh[NN * 256];   // x@g kernelized features (gather source)
__device__ __align__(16) float  d_Yr[NN * CC];    // x@(root+dense)
__device__ __align__(16) float  d_msg[NN * CC];   // scatter-add target
__device__ float  d_cnt[NN];                      // per-dst edge counts (layer-invariant)
__device__ __align__(16) float  d_h[NN * CC];     // layer-0 raw output (pre-BN)
__device__ double d_stats[2 * CC];
__device__ __align__(16) float  d_bnA[CC];
__device__ __align__(16) float  d_bnB[CC];

// ---------------- mma helpers ----------------
__device__ __forceinline__ void mma16816(float* c, const uint32_t* a, const uint32_t* b) {
    asm volatile(
        "mma.sync.aligned.m16n8k16.row.col.f32.f16.f16.f32 "
        "{%0,%1,%2,%3}, {%4,%5,%6,%7}, {%8,%9}, {%0,%1,%2,%3};"
        : "+f"(c[0]), "+f"(c[1]), "+f"(c[2]), "+f"(c[3])
        : "r"(a[0]), "r"(a[1]), "r"(a[2]), "r"(a[3]), "r"(b[0]), "r"(b[1]));
}
__device__ __forceinline__ void ldsm_x4(uint32_t* r, const __half* p) {
    uint32_t addr = (uint32_t)__cvta_generic_to_shared(p);
    asm volatile("ldmatrix.sync.aligned.m8n8.x4.shared.b16 {%0,%1,%2,%3}, [%4];"
                 : "=r"(r[0]), "=r"(r[1]), "=r"(r[2]), "=r"(r[3]) : "r"(addr));
}
__device__ __forceinline__ void ldsm_x4_trans(uint32_t* r, const __half* p) {
    uint32_t addr = (uint32_t)__cvta_generic_to_shared(p);
    asm volatile("ldmatrix.sync.aligned.m8n8.x4.trans.shared.b16 {%0,%1,%2,%3}, [%4];"
                 : "=r"(r[0]), "=r"(r[1]), "=r"(r[2]), "=r"(r[3]) : "r"(addr));
}

// ---------------- prep + zero (fused) ----------------
__global__ void prepzero_kernel(const float* __restrict__ g, const float* __restrict__ root,
                                const float* __restrict__ dense, const float* __restrict__ mu,
                                const float* __restrict__ sigma, int do_cnt, int n) {
    int tid = threadIdx.x + blockIdx.x * blockDim.x;
    if (tid < CC * 256) d_Wh[tid] = __float2half_rn(g[tid]);
    if (tid < CC * CC)  d_Wr[tid] = root[tid] + dense[tid];
    if (tid < 12) {
        d_gauss[tid] = mu[tid];
        float s = sigma[tid];
        d_gauss[12 + tid] = 0.5f / (1e-15f + s * s);
    }
    if (tid < n * (CC / 4))
        reinterpret_cast<float4*>(d_msg)[tid] = make_float4(0.f, 0.f, 0.f, 0.f);
    if (tid < 2 * CC) d_stats[tid] = 0.0;
    if (do_cnt && tid < n) d_cnt[tid] = 0.f;
}

// ---------------- GEMM (g part, fp16 HMMA): Yh[N,256] = half(x) @ half(g) ----------------
// Block: 128 rows x 128 cols (grid.y = 2), 256 threads = 8 warps, warp tile 16x128.
__global__ __launch_bounds__(256) void gemm_g_kernel(const float* __restrict__ Xin,
                                                     int affine, int nrows) {
    const float* X = affine ? d_h : Xin;
    __shared__ __half sA[128 * SAH];
    __shared__ __half sB[64 * SBH];
    int tid  = threadIdx.x;
    int row0 = blockIdx.x * 128;
    int col0 = blockIdx.y * 128;

    // B fill: 64 rows x 128 halves from d_Wh
    {
        int r = tid >> 2, cg = tid & 3;
        const float4* src = reinterpret_cast<const float4*>(d_Wh + r * 256 + col0 + cg * 32);
        float4* dst = reinterpret_cast<float4*>(sB + r * SBH + cg * 32);
        dst[0] = src[0]; dst[1] = src[1]; dst[2] = src[2]; dst[3] = src[3];
    }
    // A fill: 128 rows x 64 halves, optional BN+ReLU on load
#pragma unroll
    for (int i = 0; i < 8; i++) {
        int t  = tid + i * 256;
        int r  = t >> 4;
        int c4 = (t & 15) << 2;
        float4 v = make_float4(0.f, 0.f, 0.f, 0.f);
        int gr = row0 + r;
        if (gr < nrows)
            v = *reinterpret_cast<const float4*>(X + (size_t)gr * CC + c4);
        if (affine) {
            float4 a = *reinterpret_cast<const float4*>(d_bnA + c4);
            float4 b = *reinterpret_cast<const float4*>(d_bnB + c4);
            v.x = fmaxf(v.x * a.x + b.x, 0.f);
            v.y = fmaxf(v.y * a.y + b.y, 0.f);
            v.z = fmaxf(v.z * a.z + b.z, 0.f);
            v.w = fmaxf(v.w * a.w + b.w, 0.f);
        }
        *reinterpret_cast<__half2*>(sA + r * SAH + c4)     = __floats2half2_rn(v.x, v.y);
        *reinterpret_cast<__half2*>(sA + r * SAH + c4 + 2) = __floats2half2_rn(v.z, v.w);
    }
    __syncthreads();

    int w    = tid >> 5;
    int lane = tid & 31;
    int wrow = w * 16;

    float acc[16][4];
#pragma unroll
    for (int n = 0; n < 16; n++)
#pragma unroll
        for (int j = 0; j < 4; j++) acc[n][j] = 0.f;

#pragma unroll
    for (int ks = 0; ks < 4; ks++) {
        uint32_t a[4];
        ldsm_x4(a, sA + (wrow + (lane & 15)) * SAH + ks * 16 + (lane >> 4) * 8);
        const __half* brow = sB + (ks * 16 + (lane & 15)) * SBH + (lane >> 4) * 8;
#pragma unroll
        for (int np = 0; np < 8; np++) {         // pairs of n-frags via x4.trans
            uint32_t b[4];
            ldsm_x4_trans(b, brow + np * 16);
            mma16816(acc[2 * np],     a, b);
            mma16816(acc[2 * np + 1], a, b + 2);
        }
    }

    // Epilogue: write fp16. acc[n]: rows wrow + lane/4 (+8), cols n*8 + (lane%4)*2 (+1)
    int rA = row0 + wrow + (lane >> 2);
    int cB = col0 + ((lane & 3) << 1);
#pragma unroll
    for (int n = 0; n < 16; n++) {
        if (rA < nrows)
            *reinterpret_cast<__half2*>(d_Yh + (size_t)rA * 256 + cB + n * 8) =
                __floats2half2_rn(acc[n][0], acc[n][1]);
        if (rA + 8 < nrows)
            *reinterpret_cast<__half2*>(d_Yh + (size_t)(rA + 8) * 256 + cB + n * 8) =
                __floats2half2_rn(acc[n][2], acc[n][3]);
    }
}

// ---------------- GEMM (root+dense, fp32): Yr[N,64] = x @ Wr ----------------
__global__ __launch_bounds__(256) void gemm_r_kernel(const float* __restrict__ Xin,
                                                     int affine, int nrows) {
    const float* X = affine ? d_h : Xin;
    __shared__ float sA[64 * 64];
    __shared__ float sB[64 * 64];
    int tid  = threadIdx.x;
    int row0 = blockIdx.x * 64;

#pragma unroll
    for (int i = 0; i < 4; i++) {
        int t  = tid + i * 256;
        int r  = t >> 4;
        int c4 = (t & 15) << 2;
        float4 v = make_float4(0.f, 0.f, 0.f, 0.f);
        if (row0 + r < nrows)
            v = *reinterpret_cast<const float4*>(X + (size_t)(row0 + r) * CC + c4);
        if (affine) {
            float4 a = *reinterpret_cast<const float4*>(d_bnA + c4);
            float4 b = *reinterpret_cast<const float4*>(d_bnB + c4);
            v.x = fmaxf(v.x * a.x + b.x, 0.f);
            v.y = fmaxf(v.y * a.y + b.y, 0.f);
            v.z = fmaxf(v.z * a.z + b.z, 0.f);
            v.w = fmaxf(v.w * a.w + b.w, 0.f);
        }
        *reinterpret_cast<float4*>(sA + r * 64 + c4) = v;
        *reinterpret_cast<float4*>(sB + r * 64 + c4) =
            *reinterpret_cast<const float4*>(d_Wr + r * 64 + c4);
    }
    __syncthreads();

    int tx = tid & 15, ty = tid >> 4;
    float acc[4][4];
#pragma unroll
    for (int i = 0; i < 4; i++)
#pragma unroll
        for (int j = 0; j < 4; j++) acc[i][j] = 0.f;

#pragma unroll 8
    for (int k = 0; k < 64; k++) {
        float4 b = *reinterpret_cast<float4*>(sB + k * 64 + (tx << 2));
        float a0 = sA[(ty * 4 + 0) * 64 + k];
        float a1 = sA[(ty * 4 + 1) * 64 + k];
        float a2 = sA[(ty * 4 + 2) * 64 + k];
        float a3 = sA[(ty * 4 + 3) * 64 + k];
        acc[0][0] += a0 * b.x; acc[0][1] += a0 * b.y; acc[0][2] += a0 * b.z; acc[0][3] += a0 * b.w;
        acc[1][0] += a1 * b.x; acc[1][1] += a1 * b.y; acc[1][2] += a1 * b.z; acc[1][3] += a1 * b.w;
        acc[2][0] += a2 * b.x; acc[2][1] += a2 * b.y; acc[2][2] += a2 * b.z; acc[2][3] += a2 * b.w;
        acc[3][0] += a3 * b.x; acc[3][1] += a3 * b.y; acc[3][2] += a3 * b.z; acc[3][3] += a3 * b.w;
    }

#pragma unroll
    for (int i = 0; i < 4; i++) {
        int r = row0 + ty * 4 + i;
        if (r < nrows)
            *reinterpret_cast<float4*>(d_Yr + (size_t)r * CC + (tx << 2)) =
                make_float4(acc[i][0], acc[i][1], acc[i][2], acc[i][3]);
    }
}

// ---------------- edge kernel: fp16 gather, shfl weights, v4 RED ----------------
__device__ __forceinline__ void acc_h(float4& a, uint2 v, float wk) {
    __half2 h0 = *reinterpret_cast<__half2*>(&v.x);
    __half2 h1 = *reinterpret_cast<__half2*>(&v.y);
    float2 f0 = __half22float2(h0);
    float2 f1 = __half22float2(h1);
    a.x += wk * f0.x; a.y += wk * f0.y;
    a.z += wk * f1.x; a.w += wk * f1.y;
}

__global__ __launch_bounds__(256) void edge_kernel(const int* __restrict__ edges,
                                                   const float* __restrict__ pseudo,
                                                   int do_cnt, int nE) {
    int tid  = threadIdx.x + blockIdx.x * blockDim.x;
    int e    = tid >> 4;
    bool valid = (e < nE);
    if (!valid) e = nE - 1;
    int lane = threadIdx.x & 15;
    int wl   = threadIdx.x & 31;

    int src = edges[e];
    int dst = edges[nE + e];

    float w = 0.f;
    if (lane < 4) {
        float p0 = pseudo[e * 3 + 0];
        float p1 = pseudo[e * 3 + 1];
        float p2 = pseudo[e * 3 + 2];
        int k3 = lane * 3;
        float q0 = p0 - d_gauss[k3 + 0];
        float q1 = p1 - d_gauss[k3 + 1];
        float q2 = p2 - d_gauss[k3 + 2];
        float t = q0 * q0 * d_gauss[12 + k3 + 0]
                + q1 * q1 * d_gauss[12 + k3 + 1]
                + q2 * q2 * d_gauss[12 + k3 + 2];
        w = __expf(-t);
    }
    int gb = wl & 16;
    float w0 = __shfl_sync(0xffffffffu, w, gb | 0);
    float w1 = __shfl_sync(0xffffffffu, w, gb | 1);
    float w2 = __shfl_sync(0xffffffffu, w, gb | 2);
    float w3 = __shfl_sync(0xffffffffu, w, gb | 3);

    const uint2* yb = reinterpret_cast<const uint2*>(d_Yh) + (size_t)src * 64 + lane;
    float4 acc = make_float4(0.f, 0.f, 0.f, 0.f);
    uint2 v0 = __ldg(yb);
    uint2 v1 = __ldg(yb + 16);
    uint2 v2 = __ldg(yb + 32);
    uint2 v3 = __ldg(yb + 48);
    acc_h(acc, v0, w0);
    acc_h(acc, v1, w1);
    acc_h(acc, v2, w2);
    acc_h(acc, v3, w3);

    if (valid) {
        float* mp = d_msg + (size_t)dst * CC + lane * 4;
        unsigned long long gp;
        asm("cvta.to.global.u64 %0, %1;" : "=l"(gp) : "l"(mp));
        asm volatile("red.global.add.v4.f32 [%0], {%1,%2,%3,%4};"
                     :: "l"(gp), "f"(acc.x), "f"(acc.y), "f"(acc.z), "f"(acc.w) : "memory");
        if (do_cnt && lane == 0) atomicAdd(d_cnt + dst, 1.0f);
    }
}

// ---------------- finalize: mean aggregation + linear + bias; BN stats ----------------
__global__ void finalize_kernel(const float* __restrict__ bias, float* out, int to_out, int n) {
    float* H = to_out ? out : d_h;
    int c = threadIdx.x;
    int ty = threadIdx.y;
    int rbase = blockIdx.x * 128;
    float b = bias[c];
    double s = 0.0, s2 = 0.0;

    for (int i = ty; i < 128; i += 4) {
        int r = rbase + i;
        if (r < n) {
            float cv = fmaxf(d_cnt[r], 1.0f);
            float h = __fdividef(d_msg[(size_t)r * CC + c], cv)
                      + d_Yr[(size_t)r * CC + c] + b;
            H[(size_t)r * CC + c] = h;
            s += (double)h;
            s2 += (double)h * (double)h;
        }
    }

    __shared__ double sh[8][64];
    sh[ty][c] = s;
    sh[4 + ty][c] = s2;
    __syncthreads();
    if (ty == 0) {
        double t1 = sh[0][c] + sh[1][c] + sh[2][c] + sh[3][c];
        double t2 = sh[4][c] + sh[5][c] + sh[6][c] + sh[7][c];
        atomicAdd(&d_stats[c], t1);
        atomicAdd(&d_stats[CC + c], t2);
    }
}

// ---------------- BN prep ----------------
__global__ void bnprep_kernel(const float* __restrict__ gamma, const float* __restrict__ beta, int n) {
    int c = threadIdx.x;
    double mean = d_stats[c] / (double)n;
    double var  = d_stats[CC + c] / (double)n - mean * mean;
    double inv  = rsqrt(var + 1e-5);
    d_bnA[c] = (float)((double)gamma[c] * inv);
    d_bnB[c] = (float)((double)beta[c] - mean * (double)gamma[c] * inv);
}

// ---------------- BN apply on final output (no ReLU) ----------------
__global__ void bnapply_kernel(float* H, int n) {
    int i = threadIdx.x + blockIdx.x * blockDim.x;
    if (i >= n * (CC / 4)) return;
    float4 v = reinterpret_cast<float4*>(H)[i];
    int c4 = (i & 15) << 2;
    float4 a = *reinterpret_cast<float4*>(d_bnA + c4);
    float4 b = *reinterpret_cast<float4*>(d_bnB + c4);
    v.x = v.x * a.x + b.x;
    v.y = v.y * a.y + b.y;
    v.z = v.z * a.z + b.z;
    v.w = v.w * a.w + b.w;
    reinterpret_cast<float4*>(H)[i] = v;
}

// ---------------- host orchestration ----------------
static void run_layer(const float* x, int affine,
                      const float* g, const float* mu, const float* sigma,
                      const float* root, const float* bias, const float* dense,
                      const float* gamma, const float* beta,
                      float* out, int to_out, int layer0,
                      int N, int E, const int* edges, const float* pseudo) {
    prepzero_kernel<<<(N * 16 + 255) / 256, 256>>>(g, root, dense, mu, sigma, layer0, N);
    gemm_g_kernel<<<dim3((N + 127) / 128, 2), 256>>>(x, affine, N);
    gemm_r_kernel<<<(N + 63) / 64, 256>>>(x, affine, N);
    edge_kernel<<<(E * 16 + 255) / 256, 256>>>(edges, pseudo, layer0, E);
    finalize_kernel<<<(N + 127) / 128, dim3(64, 4)>>>(bias, out, to_out, N);
    bnprep_kernel<<<1, 64>>>(gamma, beta, N);
}

extern "C" void kernel_launch(void* const* d_in, const int* in_sizes, int n_in,
                              void* d_out, int out_size) {
    const float* vals   = (const float*)d_in[0];
    const int*   edges  = (const int*)  d_in[1];
    const float* pseudo = (const float*)d_in[2];

    const float* g0     = (const float*)d_in[3];
    const float* mu0    = (const float*)d_in[4];
    const float* sigma0 = (const float*)d_in[5];
    const float* root0  = (const float*)d_in[6];
    const float* bias0  = (const float*)d_in[7];
    const float* dense0 = (const float*)d_in[8];
    const float* gamma0 = (const float*)d_in[9];
    const float* beta0  = (const float*)d_in[10];

    const float* g1     = (const float*)d_in[11];
    const float* mu1    = (const float*)d_in[12];
    const float* sigma1 = (const float*)d_in[13];
    const float* root1  = (const float*)d_in[14];
    const float* bias1  = (const float*)d_in[15];
    const float* dense1 = (const float*)d_in[16];
    const float* gamma1 = (const float*)d_in[17];
    const float* beta1  = (const float*)d_in[18];

    float* out = (float*)d_out;

    int N = in_sizes[0] / CC;
    int E = in_sizes[1] / 2;

    // layer 0: vals -> d_h raw; BN params computed, BN+ReLU folded into layer-1 loads
    run_layer(vals, /*affine=*/0, g0, mu0, sigma0, root0, bias0, dense0, gamma0, beta0,
              out, /*to_out=*/0, /*layer0=*/1, N, E, edges, pseudo);
    // layer 1: d_h (affine+relu on load) -> out raw, then final BN
    run_layer(nullptr, /*affine=*/1, g1, mu1, sigma1, root1, bias1, dense1, gamma1, beta1,
              out, /*to_out=*/1, /*layer0=*/0, N, E, edges, pseudo);
    bnapply_kernel<<<(N * 16 + 255) / 256, 256>>>(out, N);
}